// round 1
// baseline (speedup 1.0000x reference)
#include <cuda_runtime.h>

#define BB 128
#define TT 256
#define ND 128   // NDIM = KDIM = VDIM
#define FF 2048
#define OD 4096  // ODIM*NDIM

// scratch (device globals, no allocation)
__device__ float g_q[BB*TT*ND];
__device__ float g_k[BB*TT*ND];
__device__ float g_v[BB*TT*ND];
__device__ float g_sc[BB*TT*TT];
__device__ float g_r[BB*TT*ND];
__device__ float g_h1[BB*FF];
__device__ float g_h2[BB*FF];

// ---------------------------------------------------------------------------
// Kernel 1: fused QKV projection.  grid (BT/64, 3), block 256 (16x16 logical)
// out[m, j] = sum_i X[m,i] * W[i,j] + b[j],  m in [0, B*T), 64-row tiles.
// ---------------------------------------------------------------------------
__global__ __launch_bounds__(256) void proj_kernel(
    const float* __restrict__ X,
    const float* __restrict__ Qw, const float* __restrict__ Qb,
    const float* __restrict__ Kw, const float* __restrict__ Kb,
    const float* __restrict__ Vw, const float* __restrict__ Vb)
{
    const float* W; const float* bias; float* out;
    if (blockIdx.y == 0)      { W = Qw; bias = Qb; out = g_q; }
    else if (blockIdx.y == 1) { W = Kw; bias = Kb; out = g_k; }
    else                      { W = Vw; bias = Vb; out = g_v; }

    __shared__ float Xs[64][33];
    __shared__ float Ws[32][128];

    const int tid = threadIdx.x;
    const int tx = tid & 15;      // col group
    const int ty = tid >> 4;      // row group
    const int m0 = blockIdx.x * 64;

    float acc[4][8];
#pragma unroll
    for (int i = 0; i < 4; i++)
#pragma unroll
        for (int j = 0; j < 8; j++) acc[i][j] = 0.f;

    for (int kk = 0; kk < ND; kk += 32) {
        // load X tile 64x32
        for (int e = tid; e < 64 * 32; e += 256) {
            int r = e >> 5, k = e & 31;
            Xs[r][k] = X[(m0 + r) * ND + kk + k];
        }
        // load W tile 32x128
        for (int e = tid; e < 32 * 128; e += 256) {
            int kr = e >> 7, c = e & 127;
            Ws[kr][c] = W[(kk + kr) * ND + c];
        }
        __syncthreads();
#pragma unroll
        for (int k = 0; k < 32; k++) {
            float a[4], b[8];
#pragma unroll
            for (int i = 0; i < 4; i++) a[i] = Xs[ty + 16 * i][k];
#pragma unroll
            for (int j = 0; j < 8; j++) b[j] = Ws[k][tx + 16 * j];
#pragma unroll
            for (int i = 0; i < 4; i++)
#pragma unroll
                for (int j = 0; j < 8; j++) acc[i][j] += a[i] * b[j];
        }
        __syncthreads();
    }
#pragma unroll
    for (int i = 0; i < 4; i++)
#pragma unroll
        for (int j = 0; j < 8; j++) {
            int c = tx + 16 * j;
            out[(m0 + ty + 16 * i) * ND + c] = acc[i][j] + bias[c];
        }
}

// ---------------------------------------------------------------------------
// Kernel 2a: scores[b,t,s] = dot(k[b,t,:], q[b,s,:]).  grid (4,4,B), block 256
// ---------------------------------------------------------------------------
__global__ __launch_bounds__(256) void scores_kernel()
{
    __shared__ float Ks[64][33];
    __shared__ float Qs[64][33];

    const int tid = threadIdx.x;
    const int tx = tid & 15, ty = tid >> 4;
    const int t0 = blockIdx.x * 64;
    const int s0 = blockIdx.y * 64;
    const int b  = blockIdx.z;

    const float* kb = g_k + (size_t)b * TT * ND;
    const float* qb = g_q + (size_t)b * TT * ND;

    float acc[4][4];
#pragma unroll
    for (int i = 0; i < 4; i++)
#pragma unroll
        for (int j = 0; j < 4; j++) acc[i][j] = 0.f;

    for (int kk = 0; kk < ND; kk += 32) {
        for (int e = tid; e < 64 * 32; e += 256) {
            int r = e >> 5, k = e & 31;
            Ks[r][k] = kb[(t0 + r) * ND + kk + k];
            Qs[r][k] = qb[(s0 + r) * ND + kk + k];
        }
        __syncthreads();
#pragma unroll
        for (int k = 0; k < 32; k++) {
            float a[4], c[4];
#pragma unroll
            for (int i = 0; i < 4; i++) a[i] = Ks[ty + 16 * i][k];
#pragma unroll
            for (int j = 0; j < 4; j++) c[j] = Qs[tx + 16 * j][k];
#pragma unroll
            for (int i = 0; i < 4; i++)
#pragma unroll
                for (int j = 0; j < 4; j++) acc[i][j] += a[i] * c[j];
        }
        __syncthreads();
    }
    float* scb = g_sc + (size_t)b * TT * TT;
#pragma unroll
    for (int i = 0; i < 4; i++)
#pragma unroll
        for (int j = 0; j < 4; j++)
            scb[(t0 + ty + 16 * i) * TT + s0 + tx + 16 * j] = acc[i][j];
}

// ---------------------------------------------------------------------------
// Kernel 2b: softmax over last dim (256).  grid B*T, block 256
// ---------------------------------------------------------------------------
__global__ __launch_bounds__(256) void softmax_kernel()
{
    __shared__ float red[256];
    const int row = blockIdx.x;
    const int tid = threadIdx.x;
    float x = g_sc[(size_t)row * TT + tid];

    red[tid] = x;
    __syncthreads();
    for (int off = 128; off > 0; off >>= 1) {
        if (tid < off) red[tid] = fmaxf(red[tid], red[tid + off]);
        __syncthreads();
    }
    float m = red[0];
    __syncthreads();
    float e = __expf(x - m);
    red[tid] = e;
    __syncthreads();
    for (int off = 128; off > 0; off >>= 1) {
        if (tid < off) red[tid] += red[tid + off];
        __syncthreads();
    }
    g_sc[(size_t)row * TT + tid] = e / red[0];
}

// ---------------------------------------------------------------------------
// Kernel 2c: r[b,t,v] = sum_s a[b,t,s] * v[b,s,v].  grid (4, B), block 256
// ---------------------------------------------------------------------------
__global__ __launch_bounds__(256) void av_kernel()
{
    __shared__ float As[64][33];
    __shared__ float Vs[32][128];

    const int tid = threadIdx.x;
    const int tx = tid & 15, ty = tid >> 4;
    const int t0 = blockIdx.x * 64;
    const int b  = blockIdx.y;

    const float* ab = g_sc + (size_t)b * TT * TT;
    const float* vb = g_v  + (size_t)b * TT * ND;

    float acc[4][8];
#pragma unroll
    for (int i = 0; i < 4; i++)
#pragma unroll
        for (int j = 0; j < 8; j++) acc[i][j] = 0.f;

    for (int kk = 0; kk < TT; kk += 32) {
        for (int e = tid; e < 64 * 32; e += 256) {
            int r = e >> 5, k = e & 31;
            As[r][k] = ab[(t0 + r) * TT + kk + k];
        }
        for (int e = tid; e < 32 * 128; e += 256) {
            int kr = e >> 7, c = e & 127;
            Vs[kr][c] = vb[(kk + kr) * ND + c];
        }
        __syncthreads();
#pragma unroll
        for (int k = 0; k < 32; k++) {
            float a[4], b2[8];
#pragma unroll
            for (int i = 0; i < 4; i++) a[i] = As[ty + 16 * i][k];
#pragma unroll
            for (int j = 0; j < 8; j++) b2[j] = Vs[k][tx + 16 * j];
#pragma unroll
            for (int i = 0; i < 4; i++)
#pragma unroll
                for (int j = 0; j < 8; j++) acc[i][j] += a[i] * b2[j];
        }
        __syncthreads();
    }
    float* rb = g_r + (size_t)b * TT * ND;
#pragma unroll
    for (int i = 0; i < 4; i++)
#pragma unroll
        for (int j = 0; j < 8; j++)
            rb[(t0 + ty + 16 * i) * ND + tx + 16 * j] = acc[i][j];
}

// ---------------------------------------------------------------------------
// Generic split-K MLP GEMM: out[128, N] += A[128, K] @ W[K, N] (+bias on ky=0)
// grid (N/128, ksplit), block 256.  Accumulates via atomicAdd (out pre-zeroed).
// ---------------------------------------------------------------------------
__global__ __launch_bounds__(256) void mlp_kernel(
    const float* __restrict__ A, const float* __restrict__ W,
    const float* __restrict__ bias, float* __restrict__ out,
    int K, int kchunk, int N)
{
    __shared__ float As[128][33];
    __shared__ float Ws[32][128];

    const int tid = threadIdx.x;
    const int tx = tid & 15, ty = tid >> 4;
    const int n0 = blockIdx.x * 128;
    const int k0 = blockIdx.y * kchunk;

    float acc[8][8];
#pragma unroll
    for (int i = 0; i < 8; i++)
#pragma unroll
        for (int j = 0; j < 8; j++) acc[i][j] = 0.f;
    if (blockIdx.y == 0) {
#pragma unroll
        for (int j = 0; j < 8; j++) {
            float bv = bias[n0 + tx + 16 * j];
#pragma unroll
            for (int i = 0; i < 8; i++) acc[i][j] = bv;
        }
    }

    for (int kk = k0; kk < k0 + kchunk; kk += 32) {
        for (int e = tid; e < 128 * 32; e += 256) {
            int r = e >> 5, k = e & 31;
            As[r][k] = A[(size_t)r * K + kk + k];
        }
        for (int e = tid; e < 32 * 128; e += 256) {
            int kr = e >> 7, c = e & 127;
            Ws[kr][c] = W[(size_t)(kk + kr) * N + n0 + c];
        }
        __syncthreads();
#pragma unroll
        for (int k = 0; k < 32; k++) {
            float a[8], b[8];
#pragma unroll
            for (int i = 0; i < 8; i++) a[i] = As[ty + 16 * i][k];
#pragma unroll
            for (int j = 0; j < 8; j++) b[j] = Ws[k][tx + 16 * j];
#pragma unroll
            for (int i = 0; i < 8; i++)
#pragma unroll
                for (int j = 0; j < 8; j++) acc[i][j] += a[i] * b[j];
        }
        __syncthreads();
    }
#pragma unroll
    for (int i = 0; i < 8; i++)
#pragma unroll
        for (int j = 0; j < 8; j++)
            atomicAdd(&out[(size_t)(ty + 16 * i) * N + n0 + tx + 16 * j], acc[i][j]);
}

// ---------------------------------------------------------------------------
// elementwise sigmoid in place
// ---------------------------------------------------------------------------
__global__ __launch_bounds__(256) void sigmoid_kernel(float* __restrict__ x, int n)
{
    int i = blockIdx.x * 256 + threadIdx.x;
    if (i < n) x[i] = 1.f / (1.f + __expf(-x[i]));
}

extern "C" void kernel_launch(void* const* d_in, const int* in_sizes, int n_in,
                              void* d_out, int out_size)
{
    const float* X  = (const float*)d_in[0];
    const float* Qw = (const float*)d_in[1];
    const float* Qb = (const float*)d_in[2];
    const float* Kw = (const float*)d_in[3];
    const float* Kb = (const float*)d_in[4];
    const float* Vw = (const float*)d_in[5];
    const float* Vb = (const float*)d_in[6];
    const float* W1 = (const float*)d_in[7];
    const float* b1 = (const float*)d_in[8];
    const float* W2 = (const float*)d_in[9];
    const float* b2 = (const float*)d_in[10];
    const float* W3 = (const float*)d_in[11];
    const float* b3 = (const float*)d_in[12];
    float* out = (float*)d_out;

    void* h1p; void* h2p;
    cudaGetSymbolAddress(&h1p, g_h1);
    cudaGetSymbolAddress(&h2p, g_h2);
    cudaMemsetAsync(h1p, 0, (size_t)BB * FF * sizeof(float), 0);
    cudaMemsetAsync(h2p, 0, (size_t)BB * FF * sizeof(float), 0);
    cudaMemsetAsync(out, 0, (size_t)BB * OD * sizeof(float), 0);

    // QKV projections
    proj_kernel<<<dim3((BB * TT) / 64, 3), 256>>>(X, Qw, Qb, Kw, Kb, Vw, Vb);
    // attention
    scores_kernel<<<dim3(4, 4, BB), 256>>>();
    softmax_kernel<<<BB * TT, 256>>>();
    av_kernel<<<dim3(4, BB), 256>>>();

    // MLP1: r[128, 32768] @ W1[32768, 2048] + b1, sigmoid
    // retrieve device pointers to scratch for the generic GEMM
    void* rp; void* h1pp; void* h2pp;
    cudaGetSymbolAddress(&rp, g_r);
    cudaGetSymbolAddress(&h1pp, g_h1);
    cudaGetSymbolAddress(&h2pp, g_h2);

    mlp_kernel<<<dim3(FF / 128, 32), 256>>>((const float*)rp, W1, b1,
                                            (float*)h1pp, TT * ND, 1024, FF);
    sigmoid_kernel<<<(BB * FF + 255) / 256, 256>>>((float*)h1pp, BB * FF);

    // MLP2: h1[128,2048] @ W2[2048,2048] + b2, sigmoid
    mlp_kernel<<<dim3(FF / 128, 16), 256>>>((const float*)h1pp, W2, b2,
                                            (float*)h2pp, FF, 128, FF);
    sigmoid_kernel<<<(BB * FF + 255) / 256, 256>>>((float*)h2pp, BB * FF);

    // out: h2[128,2048] @ W3[2048,4096] + b3
    mlp_kernel<<<dim3(OD / 128, 8), 256>>>((const float*)h2pp, W3, b3,
                                           out, FF, 256, OD);
}

// round 7
// speedup vs baseline: 2.1186x; 2.1186x over previous
#include <cuda_runtime.h>
#include <cstdint>

#define BB 128
#define TT 256
#define ND 128   // NDIM = KDIM = VDIM
#define FF 2048
#define OD 4096  // ODIM*NDIM

// scratch (device globals, no allocation)
__device__ float g_q[BB*TT*ND];
__device__ float g_k[BB*TT*ND];
__device__ float g_v[BB*TT*ND];
__device__ float g_sc[BB*TT*TT];
__device__ float g_r[BB*TT*ND];
__device__ float g_h1[BB*FF];
__device__ float g_h2[BB*FF];

__device__ __forceinline__ uint32_t f2tf32(float x) {
    uint32_t r;
    asm("cvt.rna.tf32.f32 %0, %1;" : "=r"(r) : "f"(x));
    return r;
}

__device__ __forceinline__ void mma_tf32(float* c, const uint32_t* a, const uint32_t* b) {
    asm volatile(
        "mma.sync.aligned.m16n8k8.row.col.f32.tf32.tf32.f32 "
        "{%0,%1,%2,%3}, {%4,%5,%6,%7}, {%8,%9}, {%0,%1,%2,%3};"
        : "+f"(c[0]), "+f"(c[1]), "+f"(c[2]), "+f"(c[3])
        : "r"(a[0]), "r"(a[1]), "r"(a[2]), "r"(a[3]), "r"(b[0]), "r"(b[1]));
}

// SMEM: row stride 36 u32 (bank = 4*row + col mod 32 -> fragment loads conflict-free)
#define LDSW 36
#define STAGE_U32 (128 * LDSW)
#define GEMM_SMEM_BYTES (4 * STAGE_U32 * 4)   // As[2] + Bs[2]

// ===========================================================================
// tf32 mma.sync GEMM: out[128, N] (+)= A[128, K_total] @ W[K_total, N]
// grid (N/128, splitk), block 256 (8 warps: 4 in M x 2 in N).
// Epilogue: atomicAdd into pre-zeroed out; bias added by blockIdx.y==0 CTAs.
// ===========================================================================
__global__ __launch_bounds__(256, 1)
void gemm_tf32_kernel(const float* __restrict__ A, int lda,
                      const float* __restrict__ W, int ldn,
                      const float* __restrict__ bias,
                      float* __restrict__ out, int kchunk)
{
    extern __shared__ uint32_t smem[];
    uint32_t* As = smem;                     // [2][128*36]
    uint32_t* Bs = smem + 2 * STAGE_U32;     // [2][128*36]  (B stored [n][k])

    const int tid  = threadIdx.x;
    const int wid  = tid >> 5, lane = tid & 31;
    const int wm   = wid & 3;                // warp row  (0..3) -> 32 M-rows
    const int wn   = wid >> 2;               // warp col  (0..1) -> 64 N-cols
    const int gid  = lane >> 2, tig = lane & 3;
    const int n0   = blockIdx.x * 128;
    const int k0   = blockIdx.y * kchunk;
    const int niter = kchunk / 32;

    float c[2][8][4];
#pragma unroll
    for (int mt = 0; mt < 2; mt++)
#pragma unroll
        for (int nt = 0; nt < 8; nt++)
#pragma unroll
            for (int i = 0; i < 4; i++) c[mt][nt][i] = 0.f;

    float4 pa[4];
    float  pb[16];

    auto ldg_tiles = [&](int kk) {
#pragma unroll
        for (int s = 0; s < 4; s++) {
            int p = s * 256 + tid;
            int r = p >> 3, c4 = p & 7;
            pa[s] = *reinterpret_cast<const float4*>(&A[(size_t)r * lda + kk + c4 * 4]);
        }
#pragma unroll
        for (int s = 0; s < 4; s++) {
            int p = s * 256 + tid;
            int n = p & 127, kq = p >> 7;
            const float* wp = &W[(size_t)(kk + kq * 4) * ldn + n0 + n];
            pb[s * 4 + 0] = wp[0];
            pb[s * 4 + 1] = wp[ldn];
            pb[s * 4 + 2] = wp[2 * (size_t)ldn];
            pb[s * 4 + 3] = wp[3 * (size_t)ldn];
        }
    };
    auto sts_tiles = [&](int st) {
        uint32_t* a = As + st * STAGE_U32;
        uint32_t* b = Bs + st * STAGE_U32;
#pragma unroll
        for (int s = 0; s < 4; s++) {
            int p = s * 256 + tid;
            int r = p >> 3, c4 = p & 7;
            uint32_t* ap = &a[r * LDSW + c4 * 4];
            ap[0] = f2tf32(pa[s].x); ap[1] = f2tf32(pa[s].y);
            ap[2] = f2tf32(pa[s].z); ap[3] = f2tf32(pa[s].w);
        }
#pragma unroll
        for (int s = 0; s < 4; s++) {
            int p = s * 256 + tid;
            int n = p & 127, kq = p >> 7;
            uint32_t* bp = &b[n * LDSW + kq * 4];
            bp[0] = f2tf32(pb[s * 4 + 0]); bp[1] = f2tf32(pb[s * 4 + 1]);
            bp[2] = f2tf32(pb[s * 4 + 2]); bp[3] = f2tf32(pb[s * 4 + 3]);
        }
    };

    ldg_tiles(k0);
    sts_tiles(0);
    __syncthreads();

    for (int it = 0; it < niter; ++it) {
        if (it + 1 < niter) ldg_tiles(k0 + (it + 1) * 32);

        const uint32_t* a = As + (it & 1) * STAGE_U32;
        const uint32_t* b = Bs + (it & 1) * STAGE_U32;
#pragma unroll
        for (int ks = 0; ks < 4; ks++) {
            const int kf = ks * 8;
            uint32_t af[2][4], bf[8][2];
#pragma unroll
            for (int mt = 0; mt < 2; mt++) {
                int rb = wm * 32 + mt * 16;
                af[mt][0] = a[(rb + gid) * LDSW + kf + tig];
                af[mt][1] = a[(rb + gid + 8) * LDSW + kf + tig];
                af[mt][2] = a[(rb + gid) * LDSW + kf + tig + 4];
                af[mt][3] = a[(rb + gid + 8) * LDSW + kf + tig + 4];
            }
#pragma unroll
            for (int nt = 0; nt < 8; nt++) {
                int cb = wn * 64 + nt * 8;
                bf[nt][0] = b[(cb + gid) * LDSW + kf + tig];
                bf[nt][1] = b[(cb + gid) * LDSW + kf + tig + 4];
            }
#pragma unroll
            for (int mt = 0; mt < 2; mt++)
#pragma unroll
                for (int nt = 0; nt < 8; nt++)
                    mma_tf32(c[mt][nt], af[mt], bf[nt]);
        }

        if (it + 1 < niter) sts_tiles((it + 1) & 1);
        __syncthreads();
    }

    // epilogue
    const bool addb = (blockIdx.y == 0);
#pragma unroll
    for (int mt = 0; mt < 2; mt++) {
        int row = wm * 32 + mt * 16 + gid;
#pragma unroll
        for (int nt = 0; nt < 8; nt++) {
            int col = n0 + wn * 64 + nt * 8 + 2 * tig;
            float b0v = addb ? bias[col] : 0.f;
            float b1v = addb ? bias[col + 1] : 0.f;
            atomicAdd(&out[(size_t)row * ldn + col],           c[mt][nt][0] + b0v);
            atomicAdd(&out[(size_t)row * ldn + col + 1],       c[mt][nt][1] + b1v);
            atomicAdd(&out[(size_t)(row + 8) * ldn + col],     c[mt][nt][2] + b0v);
            atomicAdd(&out[(size_t)(row + 8) * ldn + col + 1], c[mt][nt][3] + b1v);
        }
    }
}

// ===========================================================================
// Kernel 1: fused QKV projection.  grid (BT/64, 3), block 256
// ===========================================================================
__global__ __launch_bounds__(256) void proj_kernel(
    const float* __restrict__ X,
    const float* __restrict__ Qw, const float* __restrict__ Qb,
    const float* __restrict__ Kw, const float* __restrict__ Kb,
    const float* __restrict__ Vw, const float* __restrict__ Vb)
{
    const float* W; const float* bias; float* out;
    if (blockIdx.y == 0)      { W = Qw; bias = Qb; out = g_q; }
    else if (blockIdx.y == 1) { W = Kw; bias = Kb; out = g_k; }
    else                      { W = Vw; bias = Vb; out = g_v; }

    __shared__ float Xs[64][33];
    __shared__ float Ws[32][128];

    const int tid = threadIdx.x;
    const int tx = tid & 15;
    const int ty = tid >> 4;
    const int m0 = blockIdx.x * 64;

    float acc[4][8];
#pragma unroll
    for (int i = 0; i < 4; i++)
#pragma unroll
        for (int j = 0; j < 8; j++) acc[i][j] = 0.f;

    for (int kk = 0; kk < ND; kk += 32) {
        for (int e = tid; e < 64 * 32; e += 256) {
            int r = e >> 5, k = e & 31;
            Xs[r][k] = X[(m0 + r) * ND + kk + k];
        }
        for (int e = tid; e < 32 * 128; e += 256) {
            int kr = e >> 7, cc = e & 127;
            Ws[kr][cc] = W[(kk + kr) * ND + cc];
        }
        __syncthreads();
#pragma unroll
        for (int k = 0; k < 32; k++) {
            float a[4], b[8];
#pragma unroll
            for (int i = 0; i < 4; i++) a[i] = Xs[ty + 16 * i][k];
#pragma unroll
            for (int j = 0; j < 8; j++) b[j] = Ws[k][tx + 16 * j];
#pragma unroll
            for (int i = 0; i < 4; i++)
#pragma unroll
                for (int j = 0; j < 8; j++) acc[i][j] += a[i] * b[j];
        }
        __syncthreads();
    }
#pragma unroll
    for (int i = 0; i < 4; i++)
#pragma unroll
        for (int j = 0; j < 8; j++) {
            int cc = tx + 16 * j;
            out[(m0 + ty + 16 * i) * ND + cc] = acc[i][j] + bias[cc];
        }
}

// ===========================================================================
// Kernel 2a: scores[b,t,s] = dot(k[b,t,:], q[b,s,:]).  grid (4,4,B)
// ===========================================================================
__global__ __launch_bounds__(256) void scores_kernel()
{
    __shared__ float Ks[64][33];
    __shared__ float Qs[64][33];

    const int tid = threadIdx.x;
    const int tx = tid & 15, ty = tid >> 4;
    const int t0 = blockIdx.x * 64;
    const int s0 = blockIdx.y * 64;
    const int b  = blockIdx.z;

    const float* kb = g_k + (size_t)b * TT * ND;
    const float* qb = g_q + (size_t)b * TT * ND;

    float acc[4][4];
#pragma unroll
    for (int i = 0; i < 4; i++)
#pragma unroll
        for (int j = 0; j < 4; j++) acc[i][j] = 0.f;

    for (int kk = 0; kk < ND; kk += 32) {
        for (int e = tid; e < 64 * 32; e += 256) {
            int r = e >> 5, k = e & 31;
            Ks[r][k] = kb[(t0 + r) * ND + kk + k];
            Qs[r][k] = qb[(s0 + r) * ND + kk + k];
        }
        __syncthreads();
#pragma unroll
        for (int k = 0; k < 32; k++) {
            float a[4], cq[4];
#pragma unroll
            for (int i = 0; i < 4; i++) a[i] = Ks[ty + 16 * i][k];
#pragma unroll
            for (int j = 0; j < 4; j++) cq[j] = Qs[tx + 16 * j][k];
#pragma unroll
            for (int i = 0; i < 4; i++)
#pragma unroll
                for (int j = 0; j < 4; j++) acc[i][j] += a[i] * cq[j];
        }
        __syncthreads();
    }
    float* scb = g_sc + (size_t)b * TT * TT;
#pragma unroll
    for (int i = 0; i < 4; i++)
#pragma unroll
        for (int j = 0; j < 4; j++)
            scb[(t0 + ty + 16 * i) * TT + s0 + tx + 16 * j] = acc[i][j];
}

// ===========================================================================
// Kernel 2b: softmax over last dim (256).  grid B*T, block 256
// ===========================================================================
__global__ __launch_bounds__(256) void softmax_kernel()
{
    __shared__ float red[256];
    const int row = blockIdx.x;
    const int tid = threadIdx.x;
    float x = g_sc[(size_t)row * TT + tid];

    red[tid] = x;
    __syncthreads();
    for (int off = 128; off > 0; off >>= 1) {
        if (tid < off) red[tid] = fmaxf(red[tid], red[tid + off]);
        __syncthreads();
    }
    float m = red[0];
    __syncthreads();
    float e = __expf(x - m);
    red[tid] = e;
    __syncthreads();
    for (int off = 128; off > 0; off >>= 1) {
        if (tid < off) red[tid] += red[tid + off];
        __syncthreads();
    }
    g_sc[(size_t)row * TT + tid] = e / red[0];
}

// ===========================================================================
// Kernel 2c: r[b,t,v] = sum_s a[b,t,s] * v[b,s,v].  grid (4, B)
// ===========================================================================
__global__ __launch_bounds__(256) void av_kernel()
{
    __shared__ float As2[64][33];
    __shared__ float Vs[32][128];

    const int tid = threadIdx.x;
    const int tx = tid & 15, ty = tid >> 4;
    const int t0 = blockIdx.x * 64;
    const int b  = blockIdx.y;

    const float* ab = g_sc + (size_t)b * TT * TT;
    const float* vb = g_v  + (size_t)b * TT * ND;

    float acc[4][8];
#pragma unroll
    for (int i = 0; i < 4; i++)
#pragma unroll
        for (int j = 0; j < 8; j++) acc[i][j] = 0.f;

    for (int kk = 0; kk < TT; kk += 32) {
        for (int e = tid; e < 64 * 32; e += 256) {
            int r = e >> 5, k = e & 31;
            As2[r][k] = ab[(t0 + r) * TT + kk + k];
        }
        for (int e = tid; e < 32 * 128; e += 256) {
            int kr = e >> 7, cc = e & 127;
            Vs[kr][cc] = vb[(kk + kr) * ND + cc];
        }
        __syncthreads();
#pragma unroll
        for (int k = 0; k < 32; k++) {
            float a[4], b2[8];
#pragma unroll
            for (int i = 0; i < 4; i++) a[i] = As2[ty + 16 * i][k];
#pragma unroll
            for (int j = 0; j < 8; j++) b2[j] = Vs[k][tx + 16 * j];
#pragma unroll
            for (int i = 0; i < 4; i++)
#pragma unroll
                for (int j = 0; j < 8; j++) acc[i][j] += a[i] * b2[j];
        }
        __syncthreads();
    }
    float* rb = g_r + (size_t)b * TT * ND;
#pragma unroll
    for (int i = 0; i < 4; i++)
#pragma unroll
        for (int j = 0; j < 8; j++)
            rb[(t0 + ty + 16 * i) * ND + tx + 16 * j] = acc[i][j];
}

// ===========================================================================
// elementwise sigmoid in place
// ===========================================================================
__global__ __launch_bounds__(256) void sigmoid_kernel(float* __restrict__ x, int n)
{
    int i = blockIdx.x * 256 + threadIdx.x;
    if (i < n) x[i] = 1.f / (1.f + __expf(-x[i]));
}

extern "C" void kernel_launch(void* const* d_in, const int* in_sizes, int n_in,
                              void* d_out, int out_size)
{
    const float* X  = (const float*)d_in[0];
    const float* Qw = (const float*)d_in[1];
    const float* Qb = (const float*)d_in[2];
    const float* Kw = (const float*)d_in[3];
    const float* Kb = (const float*)d_in[4];
    const float* Vw = (const float*)d_in[5];
    const float* Vb = (const float*)d_in[6];
    const float* W1 = (const float*)d_in[7];
    const float* b1 = (const float*)d_in[8];
    const float* W2 = (const float*)d_in[9];
    const float* b2 = (const float*)d_in[10];
    const float* W3 = (const float*)d_in[11];
    const float* b3 = (const float*)d_in[12];
    float* out = (float*)d_out;

    cudaFuncSetAttribute(gemm_tf32_kernel,
                         cudaFuncAttributeMaxDynamicSharedMemorySize, GEMM_SMEM_BYTES);

    void* rp; void* h1p; void* h2p;
    cudaGetSymbolAddress(&rp,  g_r);
    cudaGetSymbolAddress(&h1p, g_h1);
    cudaGetSymbolAddress(&h2p, g_h2);
    cudaMemsetAsync(h1p, 0, (size_t)BB * FF * sizeof(float), 0);
    cudaMemsetAsync(h2p, 0, (size_t)BB * FF * sizeof(float), 0);
    cudaMemsetAsync(out, 0, (size_t)BB * OD * sizeof(float), 0);

    // QKV projections + attention (fp32, unchanged from R1)
    proj_kernel<<<dim3((BB * TT) / 64, 3), 256>>>(X, Qw, Qb, Kw, Kb, Vw, Vb);
    scores_kernel<<<dim3(4, 4, BB), 256>>>();
    softmax_kernel<<<BB * TT, 256>>>();
    av_kernel<<<dim3(4, BB), 256>>>();

    // MLP1: r[128, 32768] @ W1[32768, 2048] + b1, sigmoid   (16 N-tiles x 8 splitK)
    gemm_tf32_kernel<<<dim3(FF / 128, 8), 256, GEMM_SMEM_BYTES>>>(
        (const float*)rp, TT * ND, W1, FF, b1, (float*)h1p, (TT * ND) / 8);
    sigmoid_kernel<<<(BB * FF + 255) / 256, 256>>>((float*)h1p, BB * FF);

    // MLP2: h1[128,2048] @ W2[2048,2048] + b2, sigmoid      (16 x 8)
    gemm_tf32_kernel<<<dim3(FF / 128, 8), 256, GEMM_SMEM_BYTES>>>(
        (const float*)h1p, FF, W2, FF, b2, (float*)h2p, FF / 8);
    sigmoid_kernel<<<(BB * FF + 255) / 256, 256>>>((float*)h2p, BB * FF);

    // out: h2[128,2048] @ W3[2048,4096] + b3                (32 x 4)
    gemm_tf32_kernel<<<dim3(OD / 128, 4), 256, GEMM_SMEM_BYTES>>>(
        (const float*)h2p, FF, W3, OD, b3, out, FF / 4);
}

// round 8
// speedup vs baseline: 2.9770x; 1.4051x over previous
#include <cuda_runtime.h>
#include <cstdint>

#define BB 128
#define TT 256
#define ND 128   // NDIM = KDIM = VDIM
#define FF 2048
#define OD 4096  // ODIM*NDIM

// scratch (device globals, no allocation)
__device__ float g_q[BB*TT*ND];
__device__ float g_k[BB*TT*ND];
__device__ float g_v[BB*TT*ND];
__device__ float g_sc[BB*TT*TT];
__device__ float g_r[BB*TT*ND];
__device__ float g_h1[BB*FF];
__device__ float g_h2[BB*FF];

__device__ __forceinline__ uint32_t f2tf32(float x) {
    uint32_t r;
    asm("cvt.rna.tf32.f32 %0, %1;" : "=r"(r) : "f"(x));
    return r;
}

__device__ __forceinline__ void mma_tf32(float* c, const uint32_t* a, const uint32_t* b) {
    asm volatile(
        "mma.sync.aligned.m16n8k8.row.col.f32.tf32.tf32.f32 "
        "{%0,%1,%2,%3}, {%4,%5,%6,%7}, {%8,%9}, {%0,%1,%2,%3};"
        : "+f"(c[0]), "+f"(c[1]), "+f"(c[2]), "+f"(c[3])
        : "r"(a[0]), "r"(a[1]), "r"(a[2]), "r"(a[3]), "r"(b[0]), "r"(b[1]));
}

// SMEM: row stride 36 u32 (bank = 4*row + col mod 32 -> fragment loads conflict-free)
#define LDSW 36
#define STAGE_U32 (128 * LDSW)
#define GEMM_SMEM_BYTES (4 * STAGE_U32 * 4)   // As[2] + Bs[2]

// ===========================================================================
// split-K tf32 GEMM for skinny-M MLPs (validated R7):
// out[128, N] (+)= A[128, K_total] @ W[K_total, N]
// ===========================================================================
__global__ __launch_bounds__(256, 1)
void gemm_tf32_kernel(const float* __restrict__ A, int lda,
                      const float* __restrict__ W, int ldn,
                      const float* __restrict__ bias,
                      float* __restrict__ out, int kchunk)
{
    extern __shared__ uint32_t smem[];
    uint32_t* As = smem;
    uint32_t* Bs = smem + 2 * STAGE_U32;

    const int tid  = threadIdx.x;
    const int wid  = tid >> 5, lane = tid & 31;
    const int wm   = wid & 3;
    const int wn   = wid >> 2;
    const int gid  = lane >> 2, tig = lane & 3;
    const int n0   = blockIdx.x * 128;
    const int k0   = blockIdx.y * kchunk;
    const int niter = kchunk / 32;

    float c[2][8][4];
#pragma unroll
    for (int mt = 0; mt < 2; mt++)
#pragma unroll
        for (int nt = 0; nt < 8; nt++)
#pragma unroll
            for (int i = 0; i < 4; i++) c[mt][nt][i] = 0.f;

    float4 pa[4];
    float  pb[16];

    auto ldg_tiles = [&](int kk) {
#pragma unroll
        for (int s = 0; s < 4; s++) {
            int p = s * 256 + tid;
            int r = p >> 3, c4 = p & 7;
            pa[s] = *reinterpret_cast<const float4*>(&A[(size_t)r * lda + kk + c4 * 4]);
        }
#pragma unroll
        for (int s = 0; s < 4; s++) {
            int p = s * 256 + tid;
            int n = p & 127, kq = p >> 7;
            const float* wp = &W[(size_t)(kk + kq * 4) * ldn + n0 + n];
            pb[s * 4 + 0] = wp[0];
            pb[s * 4 + 1] = wp[ldn];
            pb[s * 4 + 2] = wp[2 * (size_t)ldn];
            pb[s * 4 + 3] = wp[3 * (size_t)ldn];
        }
    };
    auto sts_tiles = [&](int st) {
        uint32_t* a = As + st * STAGE_U32;
        uint32_t* b = Bs + st * STAGE_U32;
#pragma unroll
        for (int s = 0; s < 4; s++) {
            int p = s * 256 + tid;
            int r = p >> 3, c4 = p & 7;
            uint32_t* ap = &a[r * LDSW + c4 * 4];
            ap[0] = f2tf32(pa[s].x); ap[1] = f2tf32(pa[s].y);
            ap[2] = f2tf32(pa[s].z); ap[3] = f2tf32(pa[s].w);
        }
#pragma unroll
        for (int s = 0; s < 4; s++) {
            int p = s * 256 + tid;
            int n = p & 127, kq = p >> 7;
            uint32_t* bp = &b[n * LDSW + kq * 4];
            bp[0] = f2tf32(pb[s * 4 + 0]); bp[1] = f2tf32(pb[s * 4 + 1]);
            bp[2] = f2tf32(pb[s * 4 + 2]); bp[3] = f2tf32(pb[s * 4 + 3]);
        }
    };

    ldg_tiles(k0);
    sts_tiles(0);
    __syncthreads();

    for (int it = 0; it < niter; ++it) {
        if (it + 1 < niter) ldg_tiles(k0 + (it + 1) * 32);

        const uint32_t* a = As + (it & 1) * STAGE_U32;
        const uint32_t* b = Bs + (it & 1) * STAGE_U32;
#pragma unroll
        for (int ks = 0; ks < 4; ks++) {
            const int kf = ks * 8;
            uint32_t af[2][4], bf[8][2];
#pragma unroll
            for (int mt = 0; mt < 2; mt++) {
                int rb = wm * 32 + mt * 16;
                af[mt][0] = a[(rb + gid) * LDSW + kf + tig];
                af[mt][1] = a[(rb + gid + 8) * LDSW + kf + tig];
                af[mt][2] = a[(rb + gid) * LDSW + kf + tig + 4];
                af[mt][3] = a[(rb + gid + 8) * LDSW + kf + tig + 4];
            }
#pragma unroll
            for (int nt = 0; nt < 8; nt++) {
                int cb = wn * 64 + nt * 8;
                bf[nt][0] = b[(cb + gid) * LDSW + kf + tig];
                bf[nt][1] = b[(cb + gid) * LDSW + kf + tig + 4];
            }
#pragma unroll
            for (int mt = 0; mt < 2; mt++)
#pragma unroll
                for (int nt = 0; nt < 8; nt++)
                    mma_tf32(c[mt][nt], af[mt], bf[nt]);
        }

        if (it + 1 < niter) sts_tiles((it + 1) & 1);
        __syncthreads();
    }

    const bool addb = (blockIdx.y == 0);
#pragma unroll
    for (int mt = 0; mt < 2; mt++) {
        int row = wm * 32 + mt * 16 + gid;
#pragma unroll
        for (int nt = 0; nt < 8; nt++) {
            int col = n0 + wn * 64 + nt * 8 + 2 * tig;
            float b0v = addb ? bias[col] : 0.f;
            float b1v = addb ? bias[col + 1] : 0.f;
            atomicAdd(&out[(size_t)row * ldn + col],           c[mt][nt][0] + b0v);
            atomicAdd(&out[(size_t)row * ldn + col + 1],       c[mt][nt][1] + b1v);
            atomicAdd(&out[(size_t)(row + 8) * ldn + col],     c[mt][nt][2] + b0v);
            atomicAdd(&out[(size_t)(row + 8) * ldn + col + 1], c[mt][nt][3] + b1v);
        }
    }
}

// ===========================================================================
// batched direct-store tf32 GEMM (attention stages).
// grid (Mtiles, Ntiles, batch), block 256 (8 warps 4Mx2N).
// A: [.., M, K] row-major (lda, strideA).
// B: btrans==0 -> stored [n][k] (ldb = dist between n rows)   [scores: B=q]
//    btrans==1 -> stored [k][n] (ldb = dist between k rows)   [proj: W, av: v]
// out[(m)*ldo + n] = sum + bias[n]? ; direct store, no atomics.
// ===========================================================================
__global__ __launch_bounds__(256, 1)
void gemm_tf32_direct(const float* __restrict__ Abase, int lda, size_t strideA,
                      const float* __restrict__ Bbase, int ldb, int btrans, size_t strideB,
                      const float* __restrict__ bias,
                      float* __restrict__ Obase, int ldo, size_t strideO,
                      int K)
{
    extern __shared__ uint32_t smem[];
    uint32_t* As = smem;
    uint32_t* Bs = smem + 2 * STAGE_U32;

    const int tid  = threadIdx.x;
    const int wid  = tid >> 5, lane = tid & 31;
    const int wm   = wid & 3;
    const int wn   = wid >> 2;
    const int gid  = lane >> 2, tig = lane & 3;
    const int m0   = blockIdx.x * 128;
    const int n0   = blockIdx.y * 128;
    const int bidx = blockIdx.z;
    const int niter = K / 32;

    const float* A = Abase + (size_t)bidx * strideA + (size_t)m0 * lda;
    const float* B = Bbase + (size_t)bidx * strideB;
    float* out     = Obase + (size_t)bidx * strideO;

    float c[2][8][4];
#pragma unroll
    for (int mt = 0; mt < 2; mt++)
#pragma unroll
        for (int nt = 0; nt < 8; nt++)
#pragma unroll
            for (int i = 0; i < 4; i++) c[mt][nt][i] = 0.f;

    float4 pa[4];
    float  pb[16];

    auto ldg_tiles = [&](int kk) {
#pragma unroll
        for (int s = 0; s < 4; s++) {
            int p = s * 256 + tid;
            int r = p >> 3, c4 = p & 7;
            pa[s] = *reinterpret_cast<const float4*>(&A[(size_t)r * lda + kk + c4 * 4]);
        }
        if (btrans) {
#pragma unroll
            for (int s = 0; s < 4; s++) {
                int p = s * 256 + tid;
                int n = p & 127, kq = p >> 7;
                const float* wp = &B[(size_t)(kk + kq * 4) * ldb + n0 + n];
                pb[s * 4 + 0] = wp[0];
                pb[s * 4 + 1] = wp[ldb];
                pb[s * 4 + 2] = wp[2 * (size_t)ldb];
                pb[s * 4 + 3] = wp[3 * (size_t)ldb];
            }
        } else {
#pragma unroll
            for (int s = 0; s < 4; s++) {
                int p = s * 256 + tid;
                int r = p >> 3, c4 = p & 7;
                const float4 v = *reinterpret_cast<const float4*>(
                    &B[(size_t)(n0 + r) * ldb + kk + c4 * 4]);
                pb[s * 4 + 0] = v.x; pb[s * 4 + 1] = v.y;
                pb[s * 4 + 2] = v.z; pb[s * 4 + 3] = v.w;
            }
        }
    };
    auto sts_tiles = [&](int st) {
        uint32_t* a = As + st * STAGE_U32;
        uint32_t* b = Bs + st * STAGE_U32;
#pragma unroll
        for (int s = 0; s < 4; s++) {
            int p = s * 256 + tid;
            int r = p >> 3, c4 = p & 7;
            uint32_t* ap = &a[r * LDSW + c4 * 4];
            ap[0] = f2tf32(pa[s].x); ap[1] = f2tf32(pa[s].y);
            ap[2] = f2tf32(pa[s].z); ap[3] = f2tf32(pa[s].w);
        }
        if (btrans) {
#pragma unroll
            for (int s = 0; s < 4; s++) {
                int p = s * 256 + tid;
                int n = p & 127, kq = p >> 7;
                uint32_t* bp = &b[n * LDSW + kq * 4];
                bp[0] = f2tf32(pb[s * 4 + 0]); bp[1] = f2tf32(pb[s * 4 + 1]);
                bp[2] = f2tf32(pb[s * 4 + 2]); bp[3] = f2tf32(pb[s * 4 + 3]);
            }
        } else {
#pragma unroll
            for (int s = 0; s < 4; s++) {
                int p = s * 256 + tid;
                int r = p >> 3, c4 = p & 7;
                uint32_t* bp = &b[r * LDSW + c4 * 4];
                bp[0] = f2tf32(pb[s * 4 + 0]); bp[1] = f2tf32(pb[s * 4 + 1]);
                bp[2] = f2tf32(pb[s * 4 + 2]); bp[3] = f2tf32(pb[s * 4 + 3]);
            }
        }
    };

    ldg_tiles(0);
    sts_tiles(0);
    __syncthreads();

    for (int it = 0; it < niter; ++it) {
        if (it + 1 < niter) ldg_tiles((it + 1) * 32);

        const uint32_t* a = As + (it & 1) * STAGE_U32;
        const uint32_t* b = Bs + (it & 1) * STAGE_U32;
#pragma unroll
        for (int ks = 0; ks < 4; ks++) {
            const int kf = ks * 8;
            uint32_t af[2][4], bf[8][2];
#pragma unroll
            for (int mt = 0; mt < 2; mt++) {
                int rb = wm * 32 + mt * 16;
                af[mt][0] = a[(rb + gid) * LDSW + kf + tig];
                af[mt][1] = a[(rb + gid + 8) * LDSW + kf + tig];
                af[mt][2] = a[(rb + gid) * LDSW + kf + tig + 4];
                af[mt][3] = a[(rb + gid + 8) * LDSW + kf + tig + 4];
            }
#pragma unroll
            for (int nt = 0; nt < 8; nt++) {
                int cb = wn * 64 + nt * 8;
                bf[nt][0] = b[(cb + gid) * LDSW + kf + tig];
                bf[nt][1] = b[(cb + gid) * LDSW + kf + tig + 4];
            }
#pragma unroll
            for (int mt = 0; mt < 2; mt++)
#pragma unroll
                for (int nt = 0; nt < 8; nt++)
                    mma_tf32(c[mt][nt], af[mt], bf[nt]);
        }

        if (it + 1 < niter) sts_tiles((it + 1) & 1);
        __syncthreads();
    }

    const bool addb = (bias != nullptr);
#pragma unroll
    for (int mt = 0; mt < 2; mt++) {
        int row = m0 + wm * 32 + mt * 16 + gid;
#pragma unroll
        for (int nt = 0; nt < 8; nt++) {
            int col = n0 + wn * 64 + nt * 8 + 2 * tig;
            float b0v = addb ? bias[col] : 0.f;
            float b1v = addb ? bias[col + 1] : 0.f;
            out[(size_t)row * ldo + col]           = c[mt][nt][0] + b0v;
            out[(size_t)row * ldo + col + 1]       = c[mt][nt][1] + b1v;
            out[(size_t)(row + 8) * ldo + col]     = c[mt][nt][2] + b0v;
            out[(size_t)(row + 8) * ldo + col + 1] = c[mt][nt][3] + b1v;
        }
    }
}

// ===========================================================================
// softmax over last dim (256).  grid B*T, block 256
// ===========================================================================
__global__ __launch_bounds__(256) void softmax_kernel()
{
    __shared__ float red[256];
    const int row = blockIdx.x;
    const int tid = threadIdx.x;
    float x = g_sc[(size_t)row * TT + tid];

    red[tid] = x;
    __syncthreads();
    for (int off = 128; off > 0; off >>= 1) {
        if (tid < off) red[tid] = fmaxf(red[tid], red[tid + off]);
        __syncthreads();
    }
    float m = red[0];
    __syncthreads();
    float e = __expf(x - m);
    red[tid] = e;
    __syncthreads();
    for (int off = 128; off > 0; off >>= 1) {
        if (tid < off) red[tid] += red[tid + off];
        __syncthreads();
    }
    g_sc[(size_t)row * TT + tid] = e / red[0];
}

// ===========================================================================
// elementwise sigmoid in place
// ===========================================================================
__global__ __launch_bounds__(256) void sigmoid_kernel(float* __restrict__ x, int n)
{
    int i = blockIdx.x * 256 + threadIdx.x;
    if (i < n) x[i] = 1.f / (1.f + __expf(-x[i]));
}

extern "C" void kernel_launch(void* const* d_in, const int* in_sizes, int n_in,
                              void* d_out, int out_size)
{
    const float* X  = (const float*)d_in[0];
    const float* Qw = (const float*)d_in[1];
    const float* Qb = (const float*)d_in[2];
    const float* Kw = (const float*)d_in[3];
    const float* Kb = (const float*)d_in[4];
    const float* Vw = (const float*)d_in[5];
    const float* Vb = (const float*)d_in[6];
    const float* W1 = (const float*)d_in[7];
    const float* b1 = (const float*)d_in[8];
    const float* W2 = (const float*)d_in[9];
    const float* b2 = (const float*)d_in[10];
    const float* W3 = (const float*)d_in[11];
    const float* b3 = (const float*)d_in[12];
    float* out = (float*)d_out;

    cudaFuncSetAttribute(gemm_tf32_kernel,
                         cudaFuncAttributeMaxDynamicSharedMemorySize, GEMM_SMEM_BYTES);
    cudaFuncSetAttribute(gemm_tf32_direct,
                         cudaFuncAttributeMaxDynamicSharedMemorySize, GEMM_SMEM_BYTES);

    void* qp; void* kp; void* vp; void* scp; void* rp; void* h1p; void* h2p;
    cudaGetSymbolAddress(&qp,  g_q);
    cudaGetSymbolAddress(&kp,  g_k);
    cudaGetSymbolAddress(&vp,  g_v);
    cudaGetSymbolAddress(&scp, g_sc);
    cudaGetSymbolAddress(&rp,  g_r);
    cudaGetSymbolAddress(&h1p, g_h1);
    cudaGetSymbolAddress(&h2p, g_h2);
    cudaMemsetAsync(h1p, 0, (size_t)BB * FF * sizeof(float), 0);
    cudaMemsetAsync(h2p, 0, (size_t)BB * FF * sizeof(float), 0);
    cudaMemsetAsync(out, 0, (size_t)BB * OD * sizeof(float), 0);

    // QKV projections: X[32768,128] @ W[128,128] + b  (btrans=1, no batch)
    gemm_tf32_direct<<<dim3((BB * TT) / 128, 1, 1), 256, GEMM_SMEM_BYTES>>>(
        X, ND, 0, Qw, ND, 1, 0, Qb, (float*)qp, ND, 0, ND);
    gemm_tf32_direct<<<dim3((BB * TT) / 128, 1, 1), 256, GEMM_SMEM_BYTES>>>(
        X, ND, 0, Kw, ND, 1, 0, Kb, (float*)kp, ND, 0, ND);
    gemm_tf32_direct<<<dim3((BB * TT) / 128, 1, 1), 256, GEMM_SMEM_BYTES>>>(
        X, ND, 0, Vw, ND, 1, 0, Vb, (float*)vp, ND, 0, ND);

    // scores[b,t,s] = k[b,t,:].q[b,s,:]  (A=k row-major, B=q stored [s][k] -> btrans=0)
    gemm_tf32_direct<<<dim3(2, 2, BB), 256, GEMM_SMEM_BYTES>>>(
        (const float*)kp, ND, (size_t)TT * ND,
        (const float*)qp, ND, 0, (size_t)TT * ND,
        nullptr, (float*)scp, TT, (size_t)TT * TT, ND);

    softmax_kernel<<<BB * TT, 256>>>();

    // r[b,t,v] = a[b,t,:] @ v[b,:,v]   (A=a lda=256, B=v stored [s][v] -> btrans=1)
    gemm_tf32_direct<<<dim3(2, 1, BB), 256, GEMM_SMEM_BYTES>>>(
        (const float*)scp, TT, (size_t)TT * TT,
        (const float*)vp, ND, 1, (size_t)TT * ND,
        nullptr, (float*)rp, ND, (size_t)TT * ND, TT);

    // MLP1: r[128, 32768] @ W1[32768, 2048] + b1, sigmoid   (16 N-tiles x 8 splitK)
    gemm_tf32_kernel<<<dim3(FF / 128, 8), 256, GEMM_SMEM_BYTES>>>(
        (const float*)rp, TT * ND, W1, FF, b1, (float*)h1p, (TT * ND) / 8);
    sigmoid_kernel<<<(BB * FF + 255) / 256, 256>>>((float*)h1p, BB * FF);

    // MLP2: h1[128,2048] @ W2[2048,2048] + b2, sigmoid      (16 x 8)
    gemm_tf32_kernel<<<dim3(FF / 128, 8), 256, GEMM_SMEM_BYTES>>>(
        (const float*)h1p, FF, W2, FF, b2, (float*)h2p, FF / 8);
    sigmoid_kernel<<<(BB * FF + 255) / 256, 256>>>((float*)h2p, BB * FF);

    // out: h2[128,2048] @ W3[2048,4096] + b3                (32 x 4)
    gemm_tf32_kernel<<<dim3(OD / 128, 4), 256, GEMM_SMEM_BYTES>>>(
        (const float*)h2p, FF, W3, OD, b3, out, FF / 4);
}